// round 3
// baseline (speedup 1.0000x reference)
#include <cuda_runtime.h>

// Problem constants: B=8, N=128, IN_DIM=128, C=64 (edge dim), H=8, K=64, HK=512.

__device__ float g_Qh[1024 * 512];
__device__ float g_Kh[1024 * 512];   // pre-scaled by K^-0.5
__device__ float g_Vh[1024 * 512];
__device__ float g_Q2[1024 * 512];
__device__ float g_K2[1024 * 512];   // pre-scaled by K^-0.5
__device__ float g_sc[64 * 128 * 128]; // scores [b*8+h][i][j]
__device__ float g_mx[64];

// ---------------------------------------------------------------------------
// Kernel 1: projections. Computes h @ {Wq,Wk,Wv,Wq2,Wk2} -> g_* arrays.
// Grid (16 row-tiles of 64, 20 col-tiles of 128 over the 5*512 concat cols).
// ---------------------------------------------------------------------------
__global__ __launch_bounds__(256) void proj_kernel(
    const float* __restrict__ h,
    const float* __restrict__ Wq, const float* __restrict__ Wk,
    const float* __restrict__ Wv, const float* __restrict__ Wq2,
    const float* __restrict__ Wk2)
{
    extern __shared__ float sm[];
    float* hT = sm;              // [128 c][68 rows-padded]
    float* Ws = sm + 128 * 68;   // [128 c][132 cols-padded]
    int tid = threadIdx.x;
    int rt = blockIdx.x, ct = blockIdx.y;
    int row0 = rt * 64;
    int wsel = ct >> 2;
    int csub = (ct & 3) * 128;

    const float* W; float* dst; float scale = 1.0f;
    switch (wsel) {
        case 0:  W = Wq;  dst = g_Qh; break;
        case 1:  W = Wk;  dst = g_Kh; scale = 0.125f; break;
        case 2:  W = Wv;  dst = g_Vh; break;
        case 3:  W = Wq2; dst = g_Q2; break;
        default: W = Wk2; dst = g_K2; scale = 0.125f; break;
    }

    // Load h tile transposed: hT[c][r] = h[row0+r][c]
    for (int f4 = tid; f4 < 64 * 32; f4 += 256) {
        int r = f4 >> 5;
        int c4 = (f4 & 31) * 4;
        float4 v = *(const float4*)&h[(row0 + r) * 128 + c4];
        hT[(c4 + 0) * 68 + r] = v.x;
        hT[(c4 + 1) * 68 + r] = v.y;
        hT[(c4 + 2) * 68 + r] = v.z;
        hT[(c4 + 3) * 68 + r] = v.w;
    }
    // Load W tile: Ws[c][cc] = W[c][csub+cc]
    for (int f4 = tid; f4 < 128 * 32; f4 += 256) {
        int c = f4 >> 5;
        int cc4 = (f4 & 31) * 4;
        float4 v = *(const float4*)&W[c * 512 + csub + cc4];
        *(float4*)&Ws[c * 132 + cc4] = v;
    }
    __syncthreads();

    int rg = tid >> 4;   // 0..15, 4 rows each
    int cg = tid & 15;   // 0..15, 8 cols each
    float acc[4][8];
#pragma unroll
    for (int r = 0; r < 4; ++r)
#pragma unroll
        for (int q = 0; q < 8; ++q) acc[r][q] = 0.0f;

    for (int c = 0; c < 128; ++c) {
        float4 hv = *(const float4*)&hT[c * 68 + rg * 4];
        float4 w0 = *(const float4*)&Ws[c * 132 + cg * 8];
        float4 w1 = *(const float4*)&Ws[c * 132 + cg * 8 + 4];
        float hr[4] = {hv.x, hv.y, hv.z, hv.w};
        float wq[8] = {w0.x, w0.y, w0.z, w0.w, w1.x, w1.y, w1.z, w1.w};
#pragma unroll
        for (int r = 0; r < 4; ++r)
#pragma unroll
            for (int q = 0; q < 8; ++q) acc[r][q] += hr[r] * wq[q];
    }

#pragma unroll
    for (int r = 0; r < 4; ++r) {
        long base = (long)(row0 + rg * 4 + r) * 512 + csub + cg * 8;
        float4 o0, o1;
        o0.x = acc[r][0] * scale; o0.y = acc[r][1] * scale;
        o0.z = acc[r][2] * scale; o0.w = acc[r][3] * scale;
        o1.x = acc[r][4] * scale; o1.y = acc[r][5] * scale;
        o1.z = acc[r][6] * scale; o1.w = acc[r][7] * scale;
        *(float4*)&dst[base] = o0;
        *(float4*)&dst[base + 4] = o1;
    }
}

// ---------------------------------------------------------------------------
// Kernel 2: fused selective scores.
// Block = (b, i). For each j: branch by adj[b,i,j]:
//   scores[b,h,i,j] = sum_k B[j,hk] * sum_c e[b,i,j,c] * (W[c,hk]*A[i,hk])
// with (A,B,W) = adj ? (Qh,Kh,We) : (Q2,K2,We2).
// j's are sorted into two lists so every thread-pair uses one weight branch.
// ---------------------------------------------------------------------------
__global__ __launch_bounds__(256, 2) void score_kernel(
    const float* __restrict__ e, const unsigned* __restrict__ adjw,
    const float* __restrict__ We, const float* __restrict__ We2)
{
    extern __shared__ float sm[];
    float* e_t = sm;                        // [64 c][132 j-padded]
    float* W1s = sm + 64 * 132;             // [64 c][80] (4 chunks of 20)
    float* W2s = W1s + 64 * 80 + 16;        // +16 pad for bank offset
    int* ish   = (int*)(W2s + 64 * 80);
    int* jlA    = ish;          // [128]
    int* jlB    = ish + 128;    // [128]
    int* slot_j = ish + 256;    // [136]
    int* pair_w = ish + 392;    // [68]
    int* cnt    = ish + 460;    // [2]

    int tid = threadIdx.x;
    int b = blockIdx.x >> 7, i = blockIdx.x & 127;
    long base_e = ((long)(b * 128 + i)) * 128 * 64;

    if (tid < 2) cnt[tid] = 0;
    __syncthreads();
    if (tid < 128) {
        unsigned a = adjw[(b * 128 + i) * 128 + tid];
        int lst = (a != 0u) ? 0 : 1;
        int pos = atomicAdd(&cnt[lst], 1);
        (lst == 0 ? jlA : jlB)[pos] = tid;
    }
    // load e row-block transposed: e_t[c][j] = e[b,i,j,c]
    for (int f4 = tid; f4 < 128 * 16; f4 += 256) {
        int j = f4 >> 4;
        int c4 = (f4 & 15) * 4;
        float4 v = *(const float4*)&e[base_e + j * 64 + c4];
        e_t[(c4 + 0) * 132 + j] = v.x;
        e_t[(c4 + 1) * 132 + j] = v.y;
        e_t[(c4 + 2) * 132 + j] = v.z;
        e_t[(c4 + 3) * 132 + j] = v.w;
    }
    __syncthreads();

    int n1 = cnt[0], n2 = cnt[1];
    int n1p = (n1 + 1) & ~1;
    int n2p = (n2 + 1) & ~1;
    int nslot = n1p + n2p;
    int npairs = nslot >> 1;
    if (tid < nslot) {
        int j, sel;
        if (tid < n1p) { sel = 0; j = jlA[tid < n1 ? tid : 0]; }
        else { sel = 1; int s2 = tid - n1p; j = jlB[s2 < n2 ? s2 : 0]; }
        slot_j[tid] = j;
        if (!(tid & 1)) pair_w[tid >> 1] = sel;
    }
    __syncthreads();

    const float* Qrow  = &g_Qh[(b * 128 + i) * 512];
    const float* Q2row = &g_Q2[(b * 128 + i) * 512];
    int kg = tid & 3;

    for (int hh = 0; hh < 8; ++hh) {
        __syncthreads();
        // Build A-folded weight tiles: W'[c][k] chunked (stride 20 per 16-k chunk)
        for (int f = tid; f < 64 * 64; f += 256) {
            int c = f >> 6, k = f & 63;
            int off = c * 80 + (k >> 4) * 20 + (k & 15);
            W1s[off] = We[c * 512 + hh * 64 + k] * Qrow[hh * 64 + k];
            W2s[off] = We2[c * 512 + hh * 64 + k] * Q2row[hh * 64 + k];
        }
        __syncthreads();

        for (int pb = 0; pb < npairs; pb += 64) {
            int p = pb + (tid >> 2);
            if (p >= npairs) p = npairs - 1;   // duplicate work; same-value stores
            int j0 = slot_j[2 * p], j1 = slot_j[2 * p + 1];
            int sel = pair_w[p];
            const float* Wp = sel ? W2s : W1s;

            float acc0[16], acc1[16];
#pragma unroll
            for (int m = 0; m < 16; ++m) { acc0[m] = 0.0f; acc1[m] = 0.0f; }

            const float* ep0 = e_t + j0;
            const float* ep1 = e_t + j1;
            const float* wp = Wp + kg * 20;
#pragma unroll 4
            for (int c = 0; c < 64; ++c) {
                float e0 = ep0[c * 132];
                float e1 = ep1[c * 132];
#pragma unroll
                for (int m = 0; m < 4; ++m) {
                    float4 w = *(const float4*)&wp[c * 80 + m * 4];
                    acc0[m * 4 + 0] += e0 * w.x;
                    acc0[m * 4 + 1] += e0 * w.y;
                    acc0[m * 4 + 2] += e0 * w.z;
                    acc0[m * 4 + 3] += e0 * w.w;
                    acc1[m * 4 + 0] += e1 * w.x;
                    acc1[m * 4 + 1] += e1 * w.y;
                    acc1[m * 4 + 2] += e1 * w.z;
                    acc1[m * 4 + 3] += e1 * w.w;
                }
            }
            const float* Bsrc = sel ? g_K2 : g_Kh;
            long b0 = (long)(b * 128 + j0) * 512 + hh * 64 + kg * 16;
            long b1 = (long)(b * 128 + j1) * 512 + hh * 64 + kg * 16;
            float s0 = 0.0f, s1 = 0.0f;
#pragma unroll
            for (int m = 0; m < 4; ++m) {
                float4 v0 = *(const float4*)&Bsrc[b0 + m * 4];
                float4 v1 = *(const float4*)&Bsrc[b1 + m * 4];
                s0 += v0.x * acc0[m * 4 + 0] + v0.y * acc0[m * 4 + 1]
                    + v0.z * acc0[m * 4 + 2] + v0.w * acc0[m * 4 + 3];
                s1 += v1.x * acc1[m * 4 + 0] + v1.y * acc1[m * 4 + 1]
                    + v1.z * acc1[m * 4 + 2] + v1.w * acc1[m * 4 + 3];
            }
            // reduce across the 4 kg lanes (lanes 4q..4q+3)
            s0 += __shfl_xor_sync(0xffffffffu, s0, 1);
            s0 += __shfl_xor_sync(0xffffffffu, s0, 2);
            s1 += __shfl_xor_sync(0xffffffffu, s1, 1);
            s1 += __shfl_xor_sync(0xffffffffu, s1, 2);
            if (kg == 0) {
                long sb = ((long)((b * 8 + hh) * 128 + i)) * 128;
                g_sc[sb + j0] = s0;
                g_sc[sb + j1] = s1;
            }
        }
    }
}

// ---------------------------------------------------------------------------
// Kernel 3: global max per (b,h)
// ---------------------------------------------------------------------------
__global__ void max_kernel()
{
    __shared__ float red[256];
    int bh = blockIdx.x;
    int tid = threadIdx.x;
    const float* p = &g_sc[(long)bh * 16384];
    float m = -1e30f;
    for (int idx = tid; idx < 16384; idx += 256) m = fmaxf(m, p[idx]);
    red[tid] = m;
    __syncthreads();
    for (int s = 128; s > 0; s >>= 1) {
        if (tid < s) red[tid] = fmaxf(red[tid], red[tid + s]);
        __syncthreads();
    }
    if (tid == 0) g_mx[bh] = red[0];
}

// ---------------------------------------------------------------------------
// Kernel 4: epilogue. p = exp(s-max)*mask_i*mask_j*k_RW; out = (p@Vh)/clip(sum p)
// Block = (b, i), loops heads.
// ---------------------------------------------------------------------------
__global__ __launch_bounds__(256) void out_kernel(
    const float* __restrict__ krw, const float* __restrict__ mask,
    float* __restrict__ out)
{
    __shared__ float p[128];
    __shared__ float sp[256];
    __shared__ float sden;
    int tid = threadIdx.x;
    int b = blockIdx.x >> 7, i = blockIdx.x & 127;
    float mi = mask[b * 128 + i];

    for (int hh = 0; hh < 8; ++hh) {
        float mx = g_mx[b * 8 + hh];
        if (tid < 128) {
            float s = g_sc[((long)((b * 8 + hh) * 128 + i)) * 128 + tid];
            p[tid] = __expf(s - mx) * mi * mask[b * 128 + tid]
                   * krw[(long)b * 16384 + i * 128 + tid];
        }
        __syncthreads();
        if (tid < 32) {
            float v = p[tid] + p[tid + 32] + p[tid + 64] + p[tid + 96];
#pragma unroll
            for (int o = 16; o; o >>= 1) v += __shfl_xor_sync(0xffffffffu, v, o);
            if (tid == 0) sden = fmaxf(v, 1e-6f);
        }
        __syncthreads();
        int k = tid & 63, part = tid >> 6;
        float a = 0.0f;
#pragma unroll 4
        for (int jj = 0; jj < 32; ++jj) {
            int j = part * 32 + jj;
            a += p[j] * g_Vh[(long)(b * 128 + j) * 512 + hh * 64 + k];
        }
        sp[tid] = a;
        __syncthreads();
        if (tid < 64)
            out[(long)(b * 128 + i) * 512 + hh * 64 + tid] =
                (sp[tid] + sp[tid + 64] + sp[tid + 128] + sp[tid + 192]) / sden;
        __syncthreads();
    }
}

// ---------------------------------------------------------------------------
extern "C" void kernel_launch(void* const* d_in, const int* in_sizes, int n_in,
                              void* d_out, int out_size)
{
    (void)in_sizes; (void)n_in; (void)out_size;
    const float*    h    = (const float*)d_in[0];
    const float*    e    = (const float*)d_in[1];
    const float*    krw  = (const float*)d_in[2];
    const float*    mask = (const float*)d_in[3];
    const unsigned* adjw = (const unsigned*)d_in[4]; // bool passed as 4-byte (f32/i32): nonzero test
    const float*    Wq   = (const float*)d_in[5];
    const float*    Wk   = (const float*)d_in[6];
    const float*    Wv   = (const float*)d_in[7];
    const float*    We   = (const float*)d_in[8];
    const float*    Wq2  = (const float*)d_in[9];
    const float*    Wk2  = (const float*)d_in[10];
    const float*    We2  = (const float*)d_in[11];
    float* out = (float*)d_out;

    cudaFuncSetAttribute(proj_kernel,
                         cudaFuncAttributeMaxDynamicSharedMemorySize, 102400);
    cudaFuncSetAttribute(score_kernel,
                         cudaFuncAttributeMaxDynamicSharedMemorySize, 76800);

    proj_kernel<<<dim3(16, 20), 256, 102400>>>(h, Wq, Wk, Wv, Wq2, Wk2);
    score_kernel<<<1024, 256, 76800>>>(e, adjw, We, We2);
    max_kernel<<<64, 256>>>();
    out_kernel<<<1024, 256>>>(krw, mask, out);
}

// round 5
// speedup vs baseline: 1.9527x; 1.9527x over previous
#include <cuda_runtime.h>

// Problem constants: B=8, N=128, IN_DIM=128, C=64 (edge dim), H=8, K=64, HK=512.

__device__ float g_Qh[1024 * 512];
__device__ float g_Kh[1024 * 512];   // pre-scaled by K^-0.5
__device__ float g_Vh[1024 * 512];
__device__ float g_Q2[1024 * 512];
__device__ float g_K2[1024 * 512];   // pre-scaled by K^-0.5
__device__ float g_sc[64 * 128 * 128]; // scores [b*8+h][i][j]
__device__ float g_mx[64];

// ---------------------------------------------------------------------------
// Helpers: tf32 convert + m16n8k8 tf32 MMA
// ---------------------------------------------------------------------------
__device__ __forceinline__ float f2tf(float x) {
    unsigned u;
    asm("cvt.rna.tf32.f32 %0, %1;" : "=r"(u) : "f"(x));
    return __uint_as_float(u);
}

__device__ __forceinline__ void mma8(float acc[4],
                                     unsigned a0, unsigned a1,
                                     unsigned a2, unsigned a3,
                                     unsigned b0, unsigned b1)
{
    asm volatile(
        "mma.sync.aligned.m16n8k8.row.col.f32.tf32.tf32.f32 "
        "{%0,%1,%2,%3}, {%4,%5,%6,%7}, {%8,%9}, {%0,%1,%2,%3};"
        : "+f"(acc[0]), "+f"(acc[1]), "+f"(acc[2]), "+f"(acc[3])
        : "r"(a0), "r"(a1), "r"(a2), "r"(a3), "r"(b0), "r"(b1));
}

// Column permutation: puts (c, c+4) at adjacent addresses so fragment loads
// are single LDS.64: perm(c) = (c&56) | ((c&3)<<1) | ((c>>2)&1)
__device__ __forceinline__ int permc(int c) {
    return (c & 56) | ((c & 3) << 1) | ((c >> 2) & 1);
}

// ---------------------------------------------------------------------------
// Kernel 1: projections. Computes h @ {Wq,Wk,Wv,Wq2,Wk2} -> g_* arrays.
// ---------------------------------------------------------------------------
__global__ __launch_bounds__(256) void proj_kernel(
    const float* __restrict__ h,
    const float* __restrict__ Wq, const float* __restrict__ Wk,
    const float* __restrict__ Wv, const float* __restrict__ Wq2,
    const float* __restrict__ Wk2)
{
    extern __shared__ float sm[];
    float* hT = sm;              // [128 c][68 rows-padded]
    float* Ws = sm + 128 * 68;   // [128 c][132 cols-padded]
    int tid = threadIdx.x;
    int rt = blockIdx.x, ct = blockIdx.y;
    int row0 = rt * 64;
    int wsel = ct >> 2;
    int csub = (ct & 3) * 128;

    const float* W; float* dst; float scale = 1.0f;
    switch (wsel) {
        case 0:  W = Wq;  dst = g_Qh; break;
        case 1:  W = Wk;  dst = g_Kh; scale = 0.125f; break;
        case 2:  W = Wv;  dst = g_Vh; break;
        case 3:  W = Wq2; dst = g_Q2; break;
        default: W = Wk2; dst = g_K2; scale = 0.125f; break;
    }

    for (int f4 = tid; f4 < 64 * 32; f4 += 256) {
        int r = f4 >> 5;
        int c4 = (f4 & 31) * 4;
        float4 v = *(const float4*)&h[(row0 + r) * 128 + c4];
        hT[(c4 + 0) * 68 + r] = v.x;
        hT[(c4 + 1) * 68 + r] = v.y;
        hT[(c4 + 2) * 68 + r] = v.z;
        hT[(c4 + 3) * 68 + r] = v.w;
    }
    for (int f4 = tid; f4 < 128 * 32; f4 += 256) {
        int c = f4 >> 5;
        int cc4 = (f4 & 31) * 4;
        float4 v = *(const float4*)&W[c * 512 + csub + cc4];
        *(float4*)&Ws[c * 132 + cc4] = v;
    }
    __syncthreads();

    int rg = tid >> 4;
    int cg = tid & 15;
    float acc[4][8];
#pragma unroll
    for (int r = 0; r < 4; ++r)
#pragma unroll
        for (int qq = 0; qq < 8; ++qq) acc[r][qq] = 0.0f;

    for (int c = 0; c < 128; ++c) {
        float4 hv = *(const float4*)&hT[c * 68 + rg * 4];
        float4 w0 = *(const float4*)&Ws[c * 132 + cg * 8];
        float4 w1 = *(const float4*)&Ws[c * 132 + cg * 8 + 4];
        float hr[4] = {hv.x, hv.y, hv.z, hv.w};
        float wq[8] = {w0.x, w0.y, w0.z, w0.w, w1.x, w1.y, w1.z, w1.w};
#pragma unroll
        for (int r = 0; r < 4; ++r)
#pragma unroll
            for (int qq = 0; qq < 8; ++qq) acc[r][qq] += hr[r] * wq[qq];
    }

#pragma unroll
    for (int r = 0; r < 4; ++r) {
        long base = (long)(row0 + rg * 4 + r) * 512 + csub + cg * 8;
        float4 o0, o1;
        o0.x = acc[r][0] * scale; o0.y = acc[r][1] * scale;
        o0.z = acc[r][2] * scale; o0.w = acc[r][3] * scale;
        o1.x = acc[r][4] * scale; o1.y = acc[r][5] * scale;
        o1.z = acc[r][6] * scale; o1.w = acc[r][7] * scale;
        *(float4*)&dst[base] = o0;
        *(float4*)&dst[base + 4] = o1;
    }
}

// ---------------------------------------------------------------------------
// Kernel 2: tensor-core scores (tf32 mma.sync).
// Block = (b, i). Per head h:
//   Wt1[k][c] = We[c,hk]*Qh[i,hk], Wt2[k][c] = We2[c,hk]*Q2[i,hk]
//   U1 = e_row @ Wt1^T, U2 = e_row @ Wt2^T   (dense, both branches)
//   scores[h,j] = adj[j] ? U1[j,:]·Kh[j,h,:] : U2[j,:]·K2[j,h,:]
// smem layout uses column permutation + pad 72 for conflict-free LDS.64.
// ---------------------------------------------------------------------------
__global__ __launch_bounds__(256, 2) void score_kernel(
    const float* __restrict__ e, const unsigned* __restrict__ adjw,
    const float* __restrict__ We, const float* __restrict__ We2)
{
    extern __shared__ float sm[];
    float* e_s = sm;                     // [128 j][72]
    float* Wt1 = e_s + 128 * 72;         // [64 k][72]
    float* Wt2 = Wt1 + 64 * 72;          // [64 k][72]
    float* q1  = Wt2 + 64 * 72;          // [512]
    float* q2  = q1 + 512;               // [512]
    int* adjs  = (int*)(q2 + 512);       // [128]

    int tid = threadIdx.x;
    int lane = tid & 31, warp = tid >> 5;
    int q = lane & 3, r = lane >> 2;
    int j0 = warp * 16;
    int b = blockIdx.x >> 7, i = blockIdx.x & 127;
    long base_e = ((long)(b * 128 + i)) * 8192;

    // Load e row-block (tf32-rounded, column-permuted)
    for (int f = tid; f < 8192; f += 256) {
        int j = f >> 6, c = f & 63;
        e_s[j * 72 + permc(c)] = f2tf(e[base_e + f]);
    }
    // Q rows + adj
    for (int t = tid; t < 512; t += 256) {
        q1[t] = g_Qh[(long)(b * 128 + i) * 512 + t];
        q2[t] = g_Q2[(long)(b * 128 + i) * 512 + t];
    }
    if (tid < 128) adjs[tid] = (adjw[(b * 128 + i) * 128 + tid] != 0u);
    __syncthreads();

    for (int hh = 0; hh < 8; ++hh) {
        // Build folded weight tiles Wt[k][c] (tf32)
        for (int f = tid; f < 4096; f += 256) {
            int c = f >> 6, k = f & 63;
            int off = k * 72 + permc(c);
            float w1 = We [c * 512 + hh * 64 + k];
            float w2 = We2[c * 512 + hh * 64 + k];
            Wt1[off] = f2tf(w1 * q1[hh * 64 + k]);
            Wt2[off] = f2tf(w2 * q2[hh * 64 + k]);
        }
        __syncthreads();

        float acc1[8][4], acc2[8][4];
#pragma unroll
        for (int s = 0; s < 8; ++s)
#pragma unroll
            for (int m = 0; m < 4; ++m) { acc1[s][m] = 0.0f; acc2[s][m] = 0.0f; }

        const unsigned* eA0 = (const unsigned*)&e_s[(j0 + r) * 72 + q * 2];
        const unsigned* eA1 = eA0 + 8 * 72;
        const unsigned* W1u = (const unsigned*)Wt1;
        const unsigned* W2u = (const unsigned*)Wt2;

        for (int kc = 0; kc < 8; ++kc) {
            uint2 A0 = *(const uint2*)(eA0 + kc * 8);   // a0 (c0), a2 (c0+4)
            uint2 A1 = *(const uint2*)(eA1 + kc * 8);   // a1, a3
#pragma unroll
            for (int s = 0; s < 8; ++s) {
                int boff = (s * 8 + r) * 72 + kc * 8 + q * 2;
                uint2 B1 = *(const uint2*)(W1u + boff);
                uint2 B2 = *(const uint2*)(W2u + boff);
                mma8(acc1[s], A0.x, A1.x, A0.y, A1.y, B1.x, B1.y);
                mma8(acc2[s], A0.x, A1.x, A0.y, A1.y, B2.x, B2.y);
            }
        }

        // Epilogue: dot with Kh/K2 (branch selected by adj), quad-reduce
        int row0 = j0 + r, row1 = row0 + 8;
        int f0 = adjs[row0], f1 = adjs[row1];
        const float* K0 = (f0 ? g_Kh : g_K2)
                        + (long)(b * 128 + row0) * 512 + hh * 64 + q * 2;
        const float* K1 = (f1 ? g_Kh : g_K2)
                        + (long)(b * 128 + row1) * 512 + hh * 64 + q * 2;
        float p0 = 0.0f, p1 = 0.0f;
#pragma unroll
        for (int s = 0; s < 8; ++s) {
            float2 k0 = *(const float2*)(K0 + s * 8);
            float2 k1 = *(const float2*)(K1 + s * 8);
            float u00 = f0 ? acc1[s][0] : acc2[s][0];
            float u01 = f0 ? acc1[s][1] : acc2[s][1];
            float u10 = f1 ? acc1[s][2] : acc2[s][2];
            float u11 = f1 ? acc1[s][3] : acc2[s][3];
            p0 += u00 * k0.x + u01 * k0.y;
            p1 += u10 * k1.x + u11 * k1.y;
        }
        p0 += __shfl_xor_sync(0xffffffffu, p0, 1);
        p0 += __shfl_xor_sync(0xffffffffu, p0, 2);
        p1 += __shfl_xor_sync(0xffffffffu, p1, 1);
        p1 += __shfl_xor_sync(0xffffffffu, p1, 2);
        if (q == 0) {
            long sb = ((long)((b * 8 + hh) * 128 + i)) * 128;
            g_sc[sb + row0] = p0;
            g_sc[sb + row1] = p1;
        }
        __syncthreads();   // Wt reuse next head
    }
}

// ---------------------------------------------------------------------------
// Kernel 3: global max per (b,h)
// ---------------------------------------------------------------------------
__global__ void max_kernel()
{
    __shared__ float red[256];
    int bh = blockIdx.x;
    int tid = threadIdx.x;
    const float* p = &g_sc[(long)bh * 16384];
    float m = -1e30f;
    for (int idx = tid; idx < 16384; idx += 256) m = fmaxf(m, p[idx]);
    red[tid] = m;
    __syncthreads();
    for (int s = 128; s > 0; s >>= 1) {
        if (tid < s) red[tid] = fmaxf(red[tid], red[tid + s]);
        __syncthreads();
    }
    if (tid == 0) g_mx[bh] = red[0];
}

// ---------------------------------------------------------------------------
// Kernel 4: epilogue. Block = (b,h). V tile staged in smem once; processes
// two softmax rows (i) per iteration.
// ---------------------------------------------------------------------------
__global__ __launch_bounds__(256) void out_kernel(
    const float* __restrict__ krw, const float* __restrict__ mask,
    float* __restrict__ out)
{
    __shared__ float Vs[8192];       // [128 j][64 k]
    __shared__ float ps[2][128];
    __shared__ float red[256];
    __shared__ float dpart[8];
    __shared__ float ms[128];
    int tid = threadIdx.x;
    int b = blockIdx.x >> 3, h = blockIdx.x & 7;

    for (int f = tid; f < 8192; f += 256) {
        int j = f >> 6, k = f & 63;
        Vs[f] = g_Vh[(long)(b * 128 + j) * 512 + h * 64 + k];
    }
    if (tid < 128) ms[tid] = mask[b * 128 + tid];
    float mx = g_mx[b * 8 + h];
    __syncthreads();

    for (int i0 = 0; i0 < 128; i0 += 2) {
        int il = tid >> 7, j = tid & 127;
        int i = i0 + il;
        float s = g_sc[((long)((b * 8 + h) * 128 + i)) * 128 + j];
        float p = __expf(s - mx) * ms[i] * ms[j]
                * krw[(long)b * 16384 + i * 128 + j];
        ps[il][j] = p;
        float v = p;
#pragma unroll
        for (int o = 16; o; o >>= 1) v += __shfl_xor_sync(0xffffffffu, v, o);
        if ((tid & 31) == 0) dpart[tid >> 5] = v;
        __syncthreads();

        int k = tid & 63, half = (tid >> 6) & 1;
        int il2 = tid >> 7;
        float a = 0.0f;
#pragma unroll 8
        for (int jj = 0; jj < 64; ++jj) {
            int jx = half * 64 + jj;
            a += ps[il2][jx] * Vs[jx * 64 + k];
        }
        red[tid] = a;
        __syncthreads();

        if (tid < 128) {
            int ilw = tid >> 6, kk = tid & 63;
            float den = fmaxf(dpart[ilw * 4] + dpart[ilw * 4 + 1]
                            + dpart[ilw * 4 + 2] + dpart[ilw * 4 + 3], 1e-6f);
            out[(long)(b * 128 + i0 + ilw) * 512 + h * 64 + kk] =
                (red[ilw * 128 + kk] + red[ilw * 128 + 64 + kk]) / den;
        }
        __syncthreads();
    }
}

// ---------------------------------------------------------------------------
extern "C" void kernel_launch(void* const* d_in, const int* in_sizes, int n_in,
                              void* d_out, int out_size)
{
    (void)in_sizes; (void)n_in; (void)out_size;
    const float*    h    = (const float*)d_in[0];
    const float*    e    = (const float*)d_in[1];
    const float*    krw  = (const float*)d_in[2];
    const float*    mask = (const float*)d_in[3];
    const unsigned* adjw = (const unsigned*)d_in[4];
    const float*    Wq   = (const float*)d_in[5];
    const float*    Wk   = (const float*)d_in[6];
    const float*    Wv   = (const float*)d_in[7];
    const float*    We   = (const float*)d_in[8];
    const float*    Wq2  = (const float*)d_in[9];
    const float*    Wk2  = (const float*)d_in[10];
    const float*    We2  = (const float*)d_in[11];
    float* out = (float*)d_out;

    cudaFuncSetAttribute(proj_kernel,
                         cudaFuncAttributeMaxDynamicSharedMemorySize, 102400);
    // score smem: (128*72 + 2*64*72 + 1024)*4 + 128*4 = 78336 B
    cudaFuncSetAttribute(score_kernel,
                         cudaFuncAttributeMaxDynamicSharedMemorySize, 78336);

    proj_kernel<<<dim3(16, 20), 256, 102400>>>(h, Wq, Wk, Wv, Wq2, Wk2);
    score_kernel<<<1024, 256, 78336>>>(e, adjw, We, We2);
    max_kernel<<<64, 256>>>();
    out_kernel<<<64, 256>>>(krw, mask, out);
}

// round 6
// speedup vs baseline: 2.1728x; 1.1127x over previous
#include <cuda_runtime.h>

// Problem constants: B=8, N=128, IN_DIM=128, C=64 (edge dim), H=8, K=64, HK=512.

__device__ float g_Qh[1024 * 512];
__device__ float g_Kh[1024 * 512];   // pre-scaled by K^-0.5
__device__ float g_Vh[1024 * 512];
__device__ float g_Q2[1024 * 512];
__device__ float g_K2[1024 * 512];   // pre-scaled by K^-0.5
__device__ float g_sc[64 * 128 * 128]; // scores [b*8+h][i][j]

// ---------------------------------------------------------------------------
// Helpers: tf32 convert + m16n8k8 tf32 MMA
// ---------------------------------------------------------------------------
__device__ __forceinline__ float f2tf(float x) {
    unsigned u;
    asm("cvt.rna.tf32.f32 %0, %1;" : "=r"(u) : "f"(x));
    return __uint_as_float(u);
}

__device__ __forceinline__ void mma8(float acc[4],
                                     unsigned a0, unsigned a1,
                                     unsigned a2, unsigned a3,
                                     unsigned b0, unsigned b1)
{
    asm volatile(
        "mma.sync.aligned.m16n8k8.row.col.f32.tf32.tf32.f32 "
        "{%0,%1,%2,%3}, {%4,%5,%6,%7}, {%8,%9}, {%0,%1,%2,%3};"
        : "+f"(acc[0]), "+f"(acc[1]), "+f"(acc[2]), "+f"(acc[3])
        : "r"(a0), "r"(a1), "r"(a2), "r"(a3), "r"(b0), "r"(b1));
}

// Column permutation: puts (c, c+4) at adjacent addresses so fragment loads
// are single LDS.64: perm(c) = (c&56) | ((c&3)<<1) | ((c>>2)&1)
__device__ __forceinline__ int permc(int c) {
    return (c & 56) | ((c & 3) << 1) | ((c >> 2) & 1);
}

// ---------------------------------------------------------------------------
// Kernel 1: projections. Computes h @ {Wq,Wk,Wv,Wq2,Wk2} -> g_* arrays.
// ---------------------------------------------------------------------------
__global__ __launch_bounds__(256) void proj_kernel(
    const float* __restrict__ h,
    const float* __restrict__ Wq, const float* __restrict__ Wk,
    const float* __restrict__ Wv, const float* __restrict__ Wq2,
    const float* __restrict__ Wk2)
{
    extern __shared__ float sm[];
    float* hT = sm;              // [128 c][68 rows-padded]
    float* Ws = sm + 128 * 68;   // [128 c][132 cols-padded]
    int tid = threadIdx.x;
    int rt = blockIdx.x, ct = blockIdx.y;
    int row0 = rt * 64;
    int wsel = ct >> 2;
    int csub = (ct & 3) * 128;

    const float* W; float* dst; float scale = 1.0f;
    switch (wsel) {
        case 0:  W = Wq;  dst = g_Qh; break;
        case 1:  W = Wk;  dst = g_Kh; scale = 0.125f; break;
        case 2:  W = Wv;  dst = g_Vh; break;
        case 3:  W = Wq2; dst = g_Q2; break;
        default: W = Wk2; dst = g_K2; scale = 0.125f; break;
    }

    for (int f4 = tid; f4 < 64 * 32; f4 += 256) {
        int r = f4 >> 5;
        int c4 = (f4 & 31) * 4;
        float4 v = *(const float4*)&h[(row0 + r) * 128 + c4];
        hT[(c4 + 0) * 68 + r] = v.x;
        hT[(c4 + 1) * 68 + r] = v.y;
        hT[(c4 + 2) * 68 + r] = v.z;
        hT[(c4 + 3) * 68 + r] = v.w;
    }
    for (int f4 = tid; f4 < 128 * 32; f4 += 256) {
        int c = f4 >> 5;
        int cc4 = (f4 & 31) * 4;
        float4 v = *(const float4*)&W[c * 512 + csub + cc4];
        *(float4*)&Ws[c * 132 + cc4] = v;
    }
    __syncthreads();

    int rg = tid >> 4;
    int cg = tid & 15;
    float acc[4][8];
#pragma unroll
    for (int r = 0; r < 4; ++r)
#pragma unroll
        for (int qq = 0; qq < 8; ++qq) acc[r][qq] = 0.0f;

    for (int c = 0; c < 128; ++c) {
        float4 hv = *(const float4*)&hT[c * 68 + rg * 4];
        float4 w0 = *(const float4*)&Ws[c * 132 + cg * 8];
        float4 w1 = *(const float4*)&Ws[c * 132 + cg * 8 + 4];
        float hr[4] = {hv.x, hv.y, hv.z, hv.w};
        float wq[8] = {w0.x, w0.y, w0.z, w0.w, w1.x, w1.y, w1.z, w1.w};
#pragma unroll
        for (int r = 0; r < 4; ++r)
#pragma unroll
            for (int qq = 0; qq < 8; ++qq) acc[r][qq] += hr[r] * wq[qq];
    }

#pragma unroll
    for (int r = 0; r < 4; ++r) {
        long base = (long)(row0 + rg * 4 + r) * 512 + csub + cg * 8;
        float4 o0, o1;
        o0.x = acc[r][0] * scale; o0.y = acc[r][1] * scale;
        o0.z = acc[r][2] * scale; o0.w = acc[r][3] * scale;
        o1.x = acc[r][4] * scale; o1.y = acc[r][5] * scale;
        o1.z = acc[r][6] * scale; o1.w = acc[r][7] * scale;
        *(float4*)&dst[base] = o0;
        *(float4*)&dst[base + 4] = o1;
    }
}

// ---------------------------------------------------------------------------
// Kernel 2: tensor-core scores (tf32 mma.sync), adjacency-sorted tiles.
// Block = (b, i). j's sorted into adj / non-adj lists, padded to 16-row
// tiles; each tile computes ONLY its branch (halves MMA + epilogue work).
// Per head h:
//   Wt1[k][c] = We[c,hk]*Qh[i,hk], Wt2[k][c] = We2[c,hk]*Q2[i,hk]
//   U_tile = e_rows @ Wt^T (tf32 MMA), scores[h,j] = U[j,:]·K[j,h,:]
// ---------------------------------------------------------------------------
__global__ __launch_bounds__(256, 2) void score_kernel(
    const float* __restrict__ e, const unsigned* __restrict__ adjw,
    const float* __restrict__ We, const float* __restrict__ We2)
{
    extern __shared__ float sm[];
    float* e_s = sm;                     // [128 j][72]
    float* Wt1 = e_s + 128 * 72;         // [64 k][72]
    float* Wt2 = Wt1 + 64 * 72;          // [64 k][72]
    float* q1  = Wt2 + 64 * 72;          // [512]
    float* q2  = q1 + 512;               // [512]
    int* jlA     = (int*)(q2 + 512);     // [128]
    int* jlB     = jlA + 128;            // [128]
    int* slot_j  = jlB + 128;            // [144]
    int* tile_sel= slot_j + 144;         // [12]
    int* cnt     = tile_sel + 12;        // [2]

    int tid = threadIdx.x;
    int lane = tid & 31, warp = tid >> 5;
    int q = lane & 3, r = lane >> 2;
    int b = blockIdx.x >> 7, i = blockIdx.x & 127;
    long base_e = ((long)(b * 128 + i)) * 8192;

    if (tid < 2) cnt[tid] = 0;
    __syncthreads();
    if (tid < 128) {
        unsigned a = adjw[(b * 128 + i) * 128 + tid];
        int lst = (a != 0u) ? 0 : 1;
        int pos = atomicAdd(&cnt[lst], 1);
        (lst == 0 ? jlA : jlB)[pos] = tid;
    }
    // Load e row-block (tf32-rounded, column-permuted)
    for (int f = tid; f < 8192; f += 256) {
        int j = f >> 6, c = f & 63;
        e_s[j * 72 + permc(c)] = f2tf(e[base_e + f]);
    }
    for (int t = tid; t < 512; t += 256) {
        q1[t] = g_Qh[(long)(b * 128 + i) * 512 + t];
        q2[t] = g_Q2[(long)(b * 128 + i) * 512 + t];
    }
    __syncthreads();

    int n1 = cnt[0], n2 = cnt[1];
    int n1p = n1 ? ((n1 + 15) & ~15) : 0;
    int n2p = n2 ? ((n2 + 15) & ~15) : 0;
    int T = (n1p + n2p) >> 4;
    if (tid < n1p) {
        slot_j[tid] = jlA[tid < n1 ? tid : n1 - 1];
    } else if (tid - n1p < n2p) {
        int s2 = tid - n1p;
        slot_j[tid] = jlB[s2 < n2 ? s2 : n2 - 1];
    }
    if (tid < T) tile_sel[tid] = (tid < (n1p >> 4)) ? 0 : 1;
    __syncthreads();

    for (int hh = 0; hh < 8; ++hh) {
        // Build folded weight tiles Wt[k][c] (tf32) for both branches
        for (int f = tid; f < 4096; f += 256) {
            int c = f >> 6, k = f & 63;
            int off = k * 72 + permc(c);
            Wt1[off] = f2tf(We [c * 512 + hh * 64 + k] * q1[hh * 64 + k]);
            Wt2[off] = f2tf(We2[c * 512 + hh * 64 + k] * q2[hh * 64 + k]);
        }
        __syncthreads();

        for (int t = warp; t < T; t += 8) {
            int j0 = slot_j[t * 16 + r];
            int j1 = slot_j[t * 16 + 8 + r];
            int sel = tile_sel[t];
            const unsigned* Wu = (const unsigned*)(sel ? Wt2 : Wt1);
            const unsigned* eA0 = (const unsigned*)&e_s[j0 * 72] + q * 2;
            const unsigned* eA1 = (const unsigned*)&e_s[j1 * 72] + q * 2;

            float acc[8][4];
#pragma unroll
            for (int s = 0; s < 8; ++s)
#pragma unroll
                for (int m = 0; m < 4; ++m) acc[s][m] = 0.0f;

            for (int kc = 0; kc < 8; ++kc) {
                uint2 A0 = *(const uint2*)(eA0 + kc * 8);
                uint2 A1 = *(const uint2*)(eA1 + kc * 8);
#pragma unroll
                for (int s = 0; s < 8; ++s) {
                    uint2 Bv = *(const uint2*)(Wu + (s * 8 + r) * 72 + kc * 8 + q * 2);
                    mma8(acc[s], A0.x, A1.x, A0.y, A1.y, Bv.x, Bv.y);
                }
            }

            // Epilogue: dot with K (uniform branch per tile), quad-reduce
            const float* Ks = sel ? g_K2 : g_Kh;
            const float* K0 = Ks + (long)(b * 128 + j0) * 512 + hh * 64 + q * 2;
            const float* K1 = Ks + (long)(b * 128 + j1) * 512 + hh * 64 + q * 2;
            float p0 = 0.0f, p1 = 0.0f;
#pragma unroll
            for (int s = 0; s < 8; ++s) {
                float2 k0 = *(const float2*)(K0 + s * 8);
                float2 k1 = *(const float2*)(K1 + s * 8);
                p0 += acc[s][0] * k0.x + acc[s][1] * k0.y;
                p1 += acc[s][2] * k1.x + acc[s][3] * k1.y;
            }
            p0 += __shfl_xor_sync(0xffffffffu, p0, 1);
            p0 += __shfl_xor_sync(0xffffffffu, p0, 2);
            p1 += __shfl_xor_sync(0xffffffffu, p1, 1);
            p1 += __shfl_xor_sync(0xffffffffu, p1, 2);
            if (q == 0) {
                long sb = ((long)((b * 8 + hh) * 128 + i)) * 128;
                g_sc[sb + j0] = p0;
                g_sc[sb + j1] = p1;
            }
        }
        __syncthreads();
    }
}

// ---------------------------------------------------------------------------
// Kernel 3: epilogue, no max subtraction (scores are O(1); the uniform shift
// cancels in the normalization). Block = (b, h, i-tile of 16). V staged in
// smem once; each warp handles 2 rows with p in registers (shfl broadcast).
// out = mi * (p@V) / clip(mi * sum p), p = exp(s)*mask_j*k_RW.
// ---------------------------------------------------------------------------
__global__ __launch_bounds__(256) void out_kernel(
    const float* __restrict__ krw, const float* __restrict__ mask,
    float* __restrict__ out)
{
    __shared__ float Vs[8192];       // [128 j][64 k]
    __shared__ float ms[128];
    int tid = threadIdx.x;
    int lane = tid & 31, warp = tid >> 5;
    int blk = blockIdx.x;
    int b = blk >> 6, h = (blk >> 3) & 7, it = blk & 7;

    for (int f = tid; f < 8192; f += 256) {
        int j = f >> 6, k = f & 63;
        Vs[f] = g_Vh[(long)(b * 128 + j) * 512 + h * 64 + k];
    }
    if (tid < 128) ms[tid] = mask[b * 128 + tid];
    __syncthreads();

#pragma unroll
    for (int rr = 0; rr < 2; ++rr) {
        int i = it * 16 + warp * 2 + rr;
        float mi = ms[i];
        float pm[4];
        float den = 0.0f;
#pragma unroll
        for (int m = 0; m < 4; ++m) {
            int j = m * 32 + lane;
            float s = g_sc[((long)((b * 8 + h) * 128 + i)) * 128 + j];
            float p = __expf(s) * ms[j] * krw[(long)b * 16384 + i * 128 + j];
            pm[m] = p;
            den += p;
        }
#pragma unroll
        for (int o = 16; o; o >>= 1) den += __shfl_xor_sync(0xffffffffu, den, o);
        den = fmaxf(den * mi, 1e-6f);

        float a0 = 0.0f, a1 = 0.0f;
#pragma unroll
        for (int m = 0; m < 4; ++m) {
#pragma unroll 8
            for (int jj = 0; jj < 32; ++jj) {
                float p = __shfl_sync(0xffffffffu, pm[m], jj);
                int j = m * 32 + jj;
                a0 += p * Vs[j * 64 + lane];
                a1 += p * Vs[j * 64 + lane + 32];
            }
        }
        float inv = mi / den;
        long ob = (long)(b * 128 + i) * 512 + h * 64;
        out[ob + lane] = a0 * inv;
        out[ob + lane + 32] = a1 * inv;
    }
}

// ---------------------------------------------------------------------------
extern "C" void kernel_launch(void* const* d_in, const int* in_sizes, int n_in,
                              void* d_out, int out_size)
{
    (void)in_sizes; (void)n_in; (void)out_size;
    const float*    h    = (const float*)d_in[0];
    const float*    e    = (const float*)d_in[1];
    const float*    krw  = (const float*)d_in[2];
    const float*    mask = (const float*)d_in[3];
    const unsigned* adjw = (const unsigned*)d_in[4];
    const float*    Wq   = (const float*)d_in[5];
    const float*    Wk   = (const float*)d_in[6];
    const float*    Wv   = (const float*)d_in[7];
    const float*    We   = (const float*)d_in[8];
    const float*    Wq2  = (const float*)d_in[9];
    const float*    Wk2  = (const float*)d_in[10];
    const float*    We2  = (const float*)d_in[11];
    float* out = (float*)d_out;

    cudaFuncSetAttribute(proj_kernel,
                         cudaFuncAttributeMaxDynamicSharedMemorySize, 102400);
    // score smem: (9216 + 4608 + 4608 + 1024)*4 + 414*4 = 79480 B
    cudaFuncSetAttribute(score_kernel,
                         cudaFuncAttributeMaxDynamicSharedMemorySize, 79480);

    proj_kernel<<<dim3(16, 20), 256, 102400>>>(h, Wq, Wk, Wv, Wq2, Wk2);
    score_kernel<<<1024, 256, 79480>>>(e, adjw, We, We2);
    out_kernel<<<512, 256>>>(krw, mask, out);
}

// round 7
// speedup vs baseline: 2.8413x; 1.3077x over previous
#include <cuda_runtime.h>

// Problem constants: B=8, N=128, IN_DIM=128, C=64 (edge dim), H=8, K=64, HK=512.

__device__ float g_Qh[1024 * 512];
__device__ float g_Kh[1024 * 512];   // pre-scaled by K^-0.5
__device__ float g_Vh[1024 * 512];
__device__ float g_Q2[1024 * 512];
__device__ float g_K2[1024 * 512];   // pre-scaled by K^-0.5
__device__ float g_sc[64 * 128 * 128]; // scores [b*8+h][i][j]
__device__ float g_WTh[5 * 512 * 128]; // transposed {Wq,Wk,Wv,Wq2,Wk2}[col][c]
__device__ float g_WTe[2 * 512 * 64];  // transposed {We,We2}[col][c]

// ---------------------------------------------------------------------------
// Helpers
// ---------------------------------------------------------------------------
__device__ __forceinline__ float f2tf(float x) {
    unsigned u;
    asm("cvt.rna.tf32.f32 %0, %1;" : "=r"(u) : "f"(x));
    return __uint_as_float(u);
}

__device__ __forceinline__ void mma8(float acc[4],
                                     unsigned a0, unsigned a1,
                                     unsigned a2, unsigned a3,
                                     unsigned b0, unsigned b1)
{
    asm volatile(
        "mma.sync.aligned.m16n8k8.row.col.f32.tf32.tf32.f32 "
        "{%0,%1,%2,%3}, {%4,%5,%6,%7}, {%8,%9}, {%0,%1,%2,%3};"
        : "+f"(acc[0]), "+f"(acc[1]), "+f"(acc[2]), "+f"(acc[3])
        : "r"(a0), "r"(a1), "r"(a2), "r"(a3), "r"(b0), "r"(b1));
}

// Within-chunk word for column c: pairs (c, c+4) adjacent for LDS.64 frags.
__device__ __forceinline__ int withinc(int c) {
    return ((c & 3) << 1) | ((c >> 2) & 1);
}

// ---------------------------------------------------------------------------
// Kernel 0: weight transpose (+scale fold for Wk/Wk2).
// mats 0..4: [128,512] -> g_WTh[m][512][128]; mats 5,6: [64,512] -> g_WTe.
// ---------------------------------------------------------------------------
__global__ __launch_bounds__(256) void transpose_kernel(
    const float* __restrict__ Wq, const float* __restrict__ Wk,
    const float* __restrict__ Wv, const float* __restrict__ Wq2,
    const float* __restrict__ Wk2, const float* __restrict__ We,
    const float* __restrict__ We2)
{
    __shared__ float t[32][33];
    int m = blockIdx.z;
    int n0 = blockIdx.x * 32, c0 = blockIdx.y * 32;
    int IN = (m < 5) ? 128 : 64;
    if (c0 >= IN) return;
    const float* src;
    float* dst;
    float scale = 1.0f;
    switch (m) {
        case 0: src = Wq;  dst = g_WTh;                break;
        case 1: src = Wk;  dst = g_WTh + 512 * 128;    scale = 0.125f; break;
        case 2: src = Wv;  dst = g_WTh + 2 * 512 * 128; break;
        case 3: src = Wq2; dst = g_WTh + 3 * 512 * 128; break;
        case 4: src = Wk2; dst = g_WTh + 4 * 512 * 128; scale = 0.125f; break;
        case 5: src = We;  dst = g_WTe;                break;
        default: src = We2; dst = g_WTe + 512 * 64;    break;
    }
    int tx = threadIdx.x & 31, ty = threadIdx.x >> 5;
#pragma unroll
    for (int i = 0; i < 4; ++i)
        t[ty + i * 8][tx] = src[(c0 + ty + i * 8) * 512 + n0 + tx] * scale;
    __syncthreads();
#pragma unroll
    for (int i = 0; i < 4; ++i)
        dst[(long)(n0 + ty + i * 8) * IN + c0 + tx] = t[tx][ty + i * 8];
}

// ---------------------------------------------------------------------------
// Kernel 1: projections via tf32 MMA. Block = (colTile64, rowTile64, mat).
// out[row][col] = sum_c h[row][c] * WT[col][c].  XOR-swizzled smem.
// ---------------------------------------------------------------------------
__global__ __launch_bounds__(256) void proj_kernel(const float* __restrict__ h)
{
    extern __shared__ float sm[];
    float* As = sm;            // [64 rows][128 words], xor-swizzled
    float* Bs = sm + 8192;     // [64 cols][128 words], xor-swizzled
    int tid = threadIdx.x;
    int lane = tid & 31, warp = tid >> 5;
    int q = lane & 3, r = lane >> 2;
    int col0 = blockIdx.x * 64, row0 = blockIdx.y * 64;
    int z = blockIdx.z;
    float* dst;
    switch (z) {
        case 0: dst = g_Qh; break;
        case 1: dst = g_Kh; break;
        case 2: dst = g_Vh; break;
        case 3: dst = g_Q2; break;
        default: dst = g_K2; break;
    }
    const float* WT = g_WTh + (long)z * 512 * 128;

    // Load A (h rows) and B (WT rows) with xor-swizzle
    for (int f = tid; f < 8192; f += 256) {
        int rr = f >> 7, c = f & 127;
        int phys = ((c >> 3) & 8) | (((c >> 3) & 7) ^ (rr & 7));
        int off = rr * 128 + (phys << 3) + withinc(c);
        As[off] = f2tf(h[(row0 + rr) * 128 + c]);
        Bs[off] = f2tf(WT[(long)(col0 + rr) * 128 + c]);
    }
    __syncthreads();

    int mt = warp >> 1;
    int nts = (warp & 1) * 4;
    float acc[4][4];
#pragma unroll
    for (int t = 0; t < 4; ++t)
#pragma unroll
        for (int m = 0; m < 4; ++m) acc[t][m] = 0.0f;

    for (int kc = 0; kc < 16; ++kc) {
        int pc = ((kc & 8) | ((kc & 7) ^ r)) << 3;
        uint2 A0 = *(const uint2*)&As[(mt * 16 + r) * 128 + pc + q * 2];
        uint2 A1 = *(const uint2*)&As[(mt * 16 + 8 + r) * 128 + pc + q * 2];
#pragma unroll
        for (int t = 0; t < 4; ++t) {
            uint2 Bv = *(const uint2*)&Bs[((nts + t) * 8 + r) * 128 + pc + q * 2];
            mma8(acc[t], A0.x, A1.x, A0.y, A1.y, Bv.x, Bv.y);
        }
    }

#pragma unroll
    for (int t = 0; t < 4; ++t) {
        long b0 = (long)(row0 + mt * 16 + r) * 512 + col0 + (nts + t) * 8 + q * 2;
        long b1 = b0 + 8L * 512;
        *(float2*)&dst[b0] = make_float2(acc[t][0], acc[t][1]);
        *(float2*)&dst[b1] = make_float2(acc[t][2], acc[t][3]);
    }
}

// ---------------------------------------------------------------------------
// Kernel 2: tensor-core scores (tf32 mma.sync), adjacency-sorted tiles,
// conflict-free xor-swizzled smem. Block = (b, i).
// e rows stored in sorted slot order so MMA A-rows are sequential.
// ---------------------------------------------------------------------------
__global__ __launch_bounds__(256, 3) void score_kernel(
    const float* __restrict__ e, const unsigned* __restrict__ adjw)
{
    extern __shared__ float sm[];
    float* e_s = sm;                 // [144 slots][64 words] xor-swizzled
    float* Wt1 = e_s + 144 * 64;     // [64 k][64 words] xor-swizzled
    float* Wt2 = Wt1 + 64 * 64;
    float* q1  = Wt2 + 64 * 64;      // [512]
    float* q2  = q1 + 512;           // [512]
    int*   cnt = (int*)(q2 + 512);   // [2]
    unsigned char* jlA      = (unsigned char*)(cnt + 2);   // [128]
    unsigned char* jlB      = jlA + 128;                   // [128]
    unsigned char* slot_j   = jlB + 128;                   // [144]
    unsigned char* tile_sel = slot_j + 144;                // [12]

    int tid = threadIdx.x;
    int lane = tid & 31, warp = tid >> 5;
    int q = lane & 3, r = lane >> 2;
    int b = blockIdx.x >> 7, i = blockIdx.x & 127;
    long base_e = ((long)(b * 128 + i)) * 8192;

    if (tid < 2) cnt[tid] = 0;
    __syncthreads();
    if (tid < 128) {
        unsigned a = adjw[(b * 128 + i) * 128 + tid];
        int lst = (a != 0u) ? 0 : 1;
        int pos = atomicAdd(&cnt[lst], 1);
        (lst == 0 ? jlA : jlB)[pos] = (unsigned char)tid;
    }
    for (int t = tid; t < 512; t += 256) {
        q1[t] = g_Qh[(long)(b * 128 + i) * 512 + t];
        q2[t] = g_Q2[(long)(b * 128 + i) * 512 + t];
    }
    __syncthreads();

    int n1 = cnt[0], n2 = cnt[1];
    int n1p = n1 ? ((n1 + 15) & ~15) : 0;
    int n2p = n2 ? ((n2 + 15) & ~15) : 0;
    int T = (n1p + n2p) >> 4;
    int nslot = T << 4;
    if (tid < n1p) {
        slot_j[tid] = jlA[tid < n1 ? tid : n1 - 1];
    } else if (tid - n1p < n2p) {
        int s2 = tid - n1p;
        slot_j[tid] = jlB[s2 < n2 ? s2 : n2 - 1];
    }
    if (tid < T) tile_sel[tid] = (tid < (n1p >> 4)) ? 0 : 1;
    __syncthreads();

    // Load e rows in sorted slot order (xor-swizzled, tf32)
    for (int f = tid; f < nslot * 64; f += 256) {
        int slot = f >> 6, c = f & 63;
        int j = slot_j[slot];
        int off = slot * 64 + ((((c >> 3) ^ (slot & 7)) << 3) | withinc(c));
        e_s[off] = f2tf(e[base_e + j * 64 + c]);
    }
    __syncthreads();

    for (int hh = 0; hh < 8; ++hh) {
        // Build folded weight tiles Wt[k][c] (tf32) from transposed We
        for (int f = tid; f < 4096; f += 256) {
            int k = f >> 6, c = f & 63;
            int off = k * 64 + ((((c >> 3) ^ (k & 7)) << 3) | withinc(c));
            Wt1[off] = f2tf(g_WTe[(hh * 64 + k) * 64 + c] * q1[hh * 64 + k]);
            Wt2[off] = f2tf(g_WTe[512 * 64 + (hh * 64 + k) * 64 + c]
                            * q2[hh * 64 + k]);
        }
        __syncthreads();

        for (int t = warp; t < T; t += 8) {
            int slot0 = t * 16 + r, slot1 = slot0 + 8;
            int sel = tile_sel[t];
            const float* Wu = sel ? Wt2 : Wt1;
            float acc[8][4];
#pragma unroll
            for (int s = 0; s < 8; ++s)
#pragma unroll
                for (int m = 0; m < 4; ++m) acc[s][m] = 0.0f;

            for (int kc = 0; kc < 8; ++kc) {
                int pc = ((kc ^ r) << 3) + q * 2;
                uint2 A0 = *(const uint2*)&e_s[slot0 * 64 + pc];
                uint2 A1 = *(const uint2*)&e_s[slot1 * 64 + pc];
#pragma unroll
                for (int s = 0; s < 8; ++s) {
                    uint2 Bv = *(const uint2*)&Wu[(s * 8 + r) * 64 + pc];
                    mma8(acc[s], A0.x, A1.x, A0.y, A1.y, Bv.x, Bv.y);
                }
            }

            // Epilogue: dot with K (uniform branch per tile), quad-reduce
            int j0 = slot_j[slot0], j1 = slot_j[slot1];
            const float* Ks = sel ? g_K2 : g_Kh;
            const float* K0 = Ks + (long)(b * 128 + j0) * 512 + hh * 64 + q * 2;
            const float* K1 = Ks + (long)(b * 128 + j1) * 512 + hh * 64 + q * 2;
            float p0 = 0.0f, p1 = 0.0f;
#pragma unroll
            for (int s = 0; s < 8; ++s) {
                float2 k0 = *(const float2*)(K0 + s * 8);
                float2 k1 = *(const float2*)(K1 + s * 8);
                p0 += acc[s][0] * k0.x + acc[s][1] * k0.y;
                p1 += acc[s][2] * k1.x + acc[s][3] * k1.y;
            }
            p0 += __shfl_xor_sync(0xffffffffu, p0, 1);
            p0 += __shfl_xor_sync(0xffffffffu, p0, 2);
            p1 += __shfl_xor_sync(0xffffffffu, p1, 1);
            p1 += __shfl_xor_sync(0xffffffffu, p1, 2);
            if (q == 0) {
                long sb = ((long)((b * 8 + hh) * 128 + i)) * 128;
                g_sc[sb + j0] = p0;
                g_sc[sb + j1] = p1;
            }
        }
        __syncthreads();
    }
}

// ---------------------------------------------------------------------------
// Kernel 3: epilogue, no max subtraction (uniform shift cancels in the
// normalization). Block = (b, h, i-tile of 16). V staged in smem once;
// each warp handles 2 rows with p in registers (shfl broadcast).
// ---------------------------------------------------------------------------
__global__ __launch_bounds__(256) void out_kernel(
    const float* __restrict__ krw, const float* __restrict__ mask,
    float* __restrict__ out)
{
    __shared__ float Vs[8192];       // [128 j][64 k]
    __shared__ float ms[128];
    int tid = threadIdx.x;
    int lane = tid & 31, warp = tid >> 5;
    int blk = blockIdx.x;
    int b = blk >> 6, h = (blk >> 3) & 7, it = blk & 7;

    for (int f = tid; f < 8192; f += 256) {
        int j = f >> 6, k = f & 63;
        Vs[f] = g_Vh[(long)(b * 128 + j) * 512 + h * 64 + k];
    }
    if (tid < 128) ms[tid] = mask[b * 128 + tid];
    __syncthreads();

#pragma unroll
    for (int rr = 0; rr < 2; ++rr) {
        int i = it * 16 + warp * 2 + rr;
        float mi = ms[i];
        float pm[4];
        float den = 0.0f;
#pragma unroll
        for (int m = 0; m < 4; ++m) {
            int j = m * 32 + lane;
            float s = g_sc[((long)((b * 8 + h) * 128 + i)) * 128 + j];
            float p = __expf(s) * ms[j] * krw[(long)b * 16384 + i * 128 + j];
            pm[m] = p;
            den += p;
        }
#pragma unroll
        for (int o = 16; o; o >>= 1) den += __shfl_xor_sync(0xffffffffu, den, o);
        den = fmaxf(den * mi, 1e-6f);

        float a0 = 0.0f, a1 = 0.0f;
#pragma unroll
        for (int m = 0; m < 4; ++m) {
#pragma unroll 8
            for (int jj = 0; jj < 32; ++jj) {
                float p = __shfl_sync(0xffffffffu, pm[m], jj);
                int j = m * 32 + jj;
                a0 += p * Vs[j * 64 + lane];
                a1 += p * Vs[j * 64 + lane + 32];
            }
        }
        float inv = mi / den;
        long ob = (long)(b * 128 + i) * 512 + h * 64;
        out[ob + lane] = a0 * inv;
        out[ob + lane + 32] = a1 * inv;
    }
}

// ---------------------------------------------------------------------------
extern "C" void kernel_launch(void* const* d_in, const int* in_sizes, int n_in,
                              void* d_out, int out_size)
{
    (void)in_sizes; (void)n_in; (void)out_size;
    const float*    h    = (const float*)d_in[0];
    const float*    e    = (const float*)d_in[1];
    const float*    krw  = (const float*)d_in[2];
    const float*    mask = (const float*)d_in[3];
    const unsigned* adjw = (const unsigned*)d_in[4];
    const float*    Wq   = (const float*)d_in[5];
    const float*    Wk   = (const float*)d_in[6];
    const float*    Wv   = (const float*)d_in[7];
    const float*    We   = (const float*)d_in[8];
    const float*    Wq2  = (const float*)d_in[9];
    const float*    Wk2  = (const float*)d_in[10];
    const float*    We2  = (const float*)d_in[11];
    float* out = (float*)d_out;

    cudaFuncSetAttribute(proj_kernel,
                         cudaFuncAttributeMaxDynamicSharedMemorySize, 65536);
    // score smem: (9216 + 4096 + 4096 + 1024)*4 + 8 + 416 = 74160 -> 74240
    cudaFuncSetAttribute(score_kernel,
                         cudaFuncAttributeMaxDynamicSharedMemorySize, 74240);

    transpose_kernel<<<dim3(16, 4, 7), 256>>>(Wq, Wk, Wv, Wq2, Wk2, We, We2);
    proj_kernel<<<dim3(8, 16, 5), 256, 65536>>>(h);
    score_kernel<<<1024, 256, 74240>>>(e, adjw);
    out_kernel<<<512, 256>>>(krw, mask, out);
}

// round 8
// speedup vs baseline: 2.9887x; 1.0519x over previous
#include <cuda_runtime.h>

// Problem constants: B=8, N=128, IN_DIM=128, C=64 (edge dim), H=8, K=64, HK=512.

__device__ float g_Qh[1024 * 512];
__device__ float g_Kh[1024 * 512];   // pre-scaled by K^-0.5
__device__ float g_Vh[1024 * 512];
__device__ float g_Q2[1024 * 512];
__device__ float g_K2[1024 * 512];   // pre-scaled by K^-0.5
__device__ float g_sc[64 * 128 * 128]; // scores [b*8+h][i][j]
__device__ float g_WTh[5 * 512 * 128]; // transposed {Wq,Wk,Wv,Wq2,Wk2}[col][c]
__device__ float g_WTe[2 * 512 * 64];  // transposed {We,We2}[col][c]

// ---------------------------------------------------------------------------
// Helpers
// ---------------------------------------------------------------------------
__device__ __forceinline__ float f2tf(float x) {
    unsigned u;
    asm("cvt.rna.tf32.f32 %0, %1;" : "=r"(u) : "f"(x));
    return __uint_as_float(u);
}

__device__ __forceinline__ void mma8(float acc[4],
                                     unsigned a0, unsigned a1,
                                     unsigned a2, unsigned a3,
                                     unsigned b0, unsigned b1)
{
    asm volatile(
        "mma.sync.aligned.m16n8k8.row.col.f32.tf32.tf32.f32 "
        "{%0,%1,%2,%3}, {%4,%5,%6,%7}, {%8,%9}, {%0,%1,%2,%3};"
        : "+f"(acc[0]), "+f"(acc[1]), "+f"(acc[2]), "+f"(acc[3])
        : "r"(a0), "r"(a1), "r"(a2), "r"(a3), "r"(b0), "r"(b1));
}

// Within-chunk word for column c: pairs (c, c+4) adjacent for LDS.64 frags.
__device__ __forceinline__ int withinc(int c) {
    return ((c & 3) << 1) | ((c >> 2) & 1);
}

// ---------------------------------------------------------------------------
// Kernel 0: weight transpose (+scale fold for Wk/Wk2).
// ---------------------------------------------------------------------------
__global__ __launch_bounds__(256) void transpose_kernel(
    const float* __restrict__ Wq, const float* __restrict__ Wk,
    const float* __restrict__ Wv, const float* __restrict__ Wq2,
    const float* __restrict__ Wk2, const float* __restrict__ We,
    const float* __restrict__ We2)
{
    __shared__ float t[32][33];
    int m = blockIdx.z;
    int n0 = blockIdx.x * 32, c0 = blockIdx.y * 32;
    int IN = (m < 5) ? 128 : 64;
    if (c0 >= IN) return;
    const float* src;
    float* dst;
    float scale = 1.0f;
    switch (m) {
        case 0: src = Wq;  dst = g_WTh;                break;
        case 1: src = Wk;  dst = g_WTh + 512 * 128;    scale = 0.125f; break;
        case 2: src = Wv;  dst = g_WTh + 2 * 512 * 128; break;
        case 3: src = Wq2; dst = g_WTh + 3 * 512 * 128; break;
        case 4: src = Wk2; dst = g_WTh + 4 * 512 * 128; scale = 0.125f; break;
        case 5: src = We;  dst = g_WTe;                break;
        default: src = We2; dst = g_WTe + 512 * 64;    break;
    }
    int tx = threadIdx.x & 31, ty = threadIdx.x >> 5;
#pragma unroll
    for (int i = 0; i < 4; ++i)
        t[ty + i * 8][tx] = src[(c0 + ty + i * 8) * 512 + n0 + tx] * scale;
    __syncthreads();
#pragma unroll
    for (int i = 0; i < 4; ++i)
        dst[(long)(n0 + ty + i * 8) * IN + c0 + tx] = t[tx][ty + i * 8];
}

// ---------------------------------------------------------------------------
// Kernel 1: projections via SPLIT tf32 MMA (3-term: hi*hi + lo*hi + hi*lo
// with lo = tf32(x - tf32(x))) -> ~fp32 accuracy on Q/K/V.
// Block = (colTile64, rowTile64, mat). K=128 in 2 chunks of 64.
// ---------------------------------------------------------------------------
__global__ __launch_bounds__(256) void proj_kernel(const float* __restrict__ h)
{
    extern __shared__ float sm[];
    float* Ah = sm;            // [64 rows][64 words] xor-swizzled
    float* Al = Ah + 4096;
    float* Bh = Al + 4096;
    float* Bl = Bh + 4096;     // 64 KB total
    int tid = threadIdx.x;
    int lane = tid & 31, warp = tid >> 5;
    int q = lane & 3, r = lane >> 2;
    int col0 = blockIdx.x * 64, row0 = blockIdx.y * 64;
    int z = blockIdx.z;
    float* dst;
    switch (z) {
        case 0: dst = g_Qh; break;
        case 1: dst = g_Kh; break;
        case 2: dst = g_Vh; break;
        case 3: dst = g_Q2; break;
        default: dst = g_K2; break;
    }
    const float* WT = g_WTh + (long)z * 512 * 128;

    int mt = warp >> 1;
    int nts = (warp & 1) * 4;
    float acc[4][4];
#pragma unroll
    for (int t = 0; t < 4; ++t)
#pragma unroll
        for (int m = 0; m < 4; ++m) acc[t][m] = 0.0f;

    for (int ck = 0; ck < 2; ++ck) {
        __syncthreads();
        for (int f = tid; f < 4096; f += 256) {
            int rr = f >> 6, c = f & 63;
            int off = rr * 64 + ((((c >> 3) ^ (rr & 7)) << 3) | withinc(c));
            float av = h[(row0 + rr) * 128 + ck * 64 + c];
            float ah = f2tf(av);
            Ah[off] = ah; Al[off] = f2tf(av - ah);
            float bv = WT[(long)(col0 + rr) * 128 + ck * 64 + c];
            float bh = f2tf(bv);
            Bh[off] = bh; Bl[off] = f2tf(bv - bh);
        }
        __syncthreads();

        for (int kc = 0; kc < 8; ++kc) {
            int pc = ((kc ^ r) << 3) + q * 2;
            int a0off = (mt * 16 + r) * 64 + pc;
            int a1off = (mt * 16 + 8 + r) * 64 + pc;
            uint2 Ah0 = *(const uint2*)&Ah[a0off];
            uint2 Ah1 = *(const uint2*)&Ah[a1off];
            uint2 Al0 = *(const uint2*)&Al[a0off];
            uint2 Al1 = *(const uint2*)&Al[a1off];
#pragma unroll
            for (int t = 0; t < 4; ++t) {
                int boff = ((nts + t) * 8 + r) * 64 + pc;
                uint2 Bhv = *(const uint2*)&Bh[boff];
                uint2 Blv = *(const uint2*)&Bl[boff];
                mma8(acc[t], Ah0.x, Ah1.x, Ah0.y, Ah1.y, Bhv.x, Bhv.y);
                mma8(acc[t], Al0.x, Al1.x, Al0.y, Al1.y, Bhv.x, Bhv.y);
                mma8(acc[t], Ah0.x, Ah1.x, Ah0.y, Ah1.y, Blv.x, Blv.y);
            }
        }
    }

#pragma unroll
    for (int t = 0; t < 4; ++t) {
        long b0 = (long)(row0 + mt * 16 + r) * 512 + col0 + (nts + t) * 8 + q * 2;
        long b1 = b0 + 8L * 512;
        *(float2*)&dst[b0] = make_float2(acc[t][0], acc[t][1]);
        *(float2*)&dst[b1] = make_float2(acc[t][2], acc[t][3]);
    }
}

// ---------------------------------------------------------------------------
// Kernel 2: tensor-core scores. 512 threads; warp = (head, k-half).
// B fragments (Q-folded We) built ONCE per branch into REGISTERS from L2;
// no smem Wt, no per-head syncs. Partial (h,j) scores from the two k-half
// warps combine via smem atomicAdd (padded slots guarded).
// ---------------------------------------------------------------------------
__global__ __launch_bounds__(512, 1) void score_kernel(
    const float* __restrict__ e, const unsigned* __restrict__ adjw)
{
    extern __shared__ float sm[];
    float* e_s  = sm;                 // [144 slots][64 words] xor-swizzled
    float* q1   = e_s + 144 * 64;     // [512]
    float* q2   = q1 + 512;           // [512]
    float* sc_s = q2 + 512;           // [8 h][128 j]
    int*   cnt  = (int*)(sc_s + 1024);
    unsigned char* jlA    = (unsigned char*)(cnt + 2);   // [128]
    unsigned char* jlB    = jlA + 128;                   // [128]
    unsigned char* slot_j = jlB + 128;                   // [144]
    unsigned char* slot_v = slot_j + 144;                // [144]

    int tid = threadIdx.x;
    int lane = tid & 31, warp = tid >> 5;
    int q = lane & 3, r = lane >> 2;
    int head = warp >> 1, half = warp & 1;
    int b = blockIdx.x >> 7, i = blockIdx.x & 127;
    long base_e = ((long)(b * 128 + i)) * 8192;

    if (tid < 2) cnt[tid] = 0;
    sc_s[tid] = 0.0f;
    sc_s[tid + 512] = 0.0f;
    __syncthreads();
    if (tid < 128) {
        unsigned a = adjw[(b * 128 + i) * 128 + tid];
        int lst = (a != 0u) ? 0 : 1;
        int pos = atomicAdd(&cnt[lst], 1);
        (lst == 0 ? jlA : jlB)[pos] = (unsigned char)tid;
    }
    q1[tid] = g_Qh[(long)(b * 128 + i) * 512 + tid];
    q2[tid] = g_Q2[(long)(b * 128 + i) * 512 + tid];
    __syncthreads();

    int n1 = cnt[0], n2 = cnt[1];
    int n1p = n1 ? ((n1 + 15) & ~15) : 0;
    int n2p = n2 ? ((n2 + 15) & ~15) : 0;
    int T1 = n1p >> 4;
    int T = (n1p + n2p) >> 4;
    int nslot = T << 4;
    if (tid < n1p) {
        slot_j[tid] = jlA[tid < n1 ? tid : n1 - 1];
        slot_v[tid] = (tid < n1);
    } else if (tid - n1p < n2p) {
        int s2 = tid - n1p;
        slot_j[tid] = jlB[s2 < n2 ? s2 : n2 - 1];
        slot_v[tid] = (s2 < n2);
    }
    __syncthreads();

    // Load e rows in sorted slot order (xor-swizzled, tf32)
    for (int f = tid; f < nslot * 64; f += 512) {
        int slot = f >> 6, c = f & 63;
        int j = slot_j[slot];
        int off = slot * 64 + ((((c >> 3) ^ (slot & 7)) << 3) | withinc(c));
        e_s[off] = f2tf(e[base_e + j * 64 + c]);
    }
    __syncthreads();

    int kbase = head * 64 + half * 32;
    for (int g = 0; g < 2; ++g) {
        int t0 = g ? T1 : 0;
        int t1 = g ? T : T1;
        if (t0 == t1) continue;
        const float* WT = g_WTe + (long)g * 512 * 64;
        const float* qs = g ? q2 : q1;

        // Build B fragments in registers: b0 = Wt[n = s*8+r][c = kc*8+q],
        // b1 = Wt[n][c = kc*8+q+4], Wt[k][c] = We^T[k][c] * Q[i][k].
        uint2 Bv[4][8];
#pragma unroll
        for (int s = 0; s < 4; ++s) {
            int krow = kbase + s * 8 + r;
            float qv = qs[krow];
            const float* wrow = WT + krow * 64;
#pragma unroll
            for (int kc = 0; kc < 8; ++kc) {
                Bv[s][kc].x = __float_as_uint(f2tf(wrow[kc * 8 + q] * qv));
                Bv[s][kc].y = __float_as_uint(f2tf(wrow[kc * 8 + q + 4] * qv));
            }
        }

        const float* Ks = g ? g_K2 : g_Kh;
        for (int t = t0; t < t1; ++t) {
            int slot0 = t * 16 + r, slot1 = slot0 + 8;
            float acc[4][4];
#pragma unroll
            for (int s = 0; s < 4; ++s)
#pragma unroll
                for (int m = 0; m < 4; ++m) acc[s][m] = 0.0f;

#pragma unroll
            for (int kc = 0; kc < 8; ++kc) {
                int pc = ((kc ^ r) << 3) + q * 2;
                uint2 A0 = *(const uint2*)&e_s[slot0 * 64 + pc];
                uint2 A1 = *(const uint2*)&e_s[slot1 * 64 + pc];
#pragma unroll
                for (int s = 0; s < 4; ++s)
                    mma8(acc[s], A0.x, A1.x, A0.y, A1.y,
                         Bv[s][kc].x, Bv[s][kc].y);
            }

            // Epilogue: dot partial k-range with K, quad-reduce, smem-add
            int j0 = slot_j[slot0], j1 = slot_j[slot1];
            const float* K0 = Ks + (long)(b * 128 + j0) * 512 + kbase + q * 2;
            const float* K1 = Ks + (long)(b * 128 + j1) * 512 + kbase + q * 2;
            float p0 = 0.0f, p1 = 0.0f;
#pragma unroll
            for (int s = 0; s < 4; ++s) {
                float2 k0 = *(const float2*)(K0 + s * 8);
                float2 k1 = *(const float2*)(K1 + s * 8);
                p0 += acc[s][0] * k0.x + acc[s][1] * k0.y;
                p1 += acc[s][2] * k1.x + acc[s][3] * k1.y;
            }
            p0 += __shfl_xor_sync(0xffffffffu, p0, 1);
            p0 += __shfl_xor_sync(0xffffffffu, p0, 2);
            p1 += __shfl_xor_sync(0xffffffffu, p1, 1);
            p1 += __shfl_xor_sync(0xffffffffu, p1, 2);
            if (q == 0) {
                if (slot_v[slot0]) atomicAdd(&sc_s[head * 128 + j0], p0);
                if (slot_v[slot1]) atomicAdd(&sc_s[head * 128 + j1], p1);
            }
        }
    }
    __syncthreads();

    for (int idx = tid; idx < 1024; idx += 512) {
        int hh = idx >> 7, j = idx & 127;
        g_sc[((long)((b * 8 + hh) * 128 + i)) * 128 + j] = sc_s[idx];
    }
}

// ---------------------------------------------------------------------------
// Kernel 3: epilogue, no max subtraction (uniform shift cancels in the
// normalization). Block = (b, h, i-tile of 16).
// ---------------------------------------------------------------------------
__global__ __launch_bounds__(256) void out_kernel(
    const float* __restrict__ krw, const float* __restrict__ mask,
    float* __restrict__ out)
{
    __shared__ float Vs[8192];       // [128 j][64 k]
    __shared__ float ms[128];
    int tid = threadIdx.x;
    int lane = tid & 31, warp = tid >> 5;
    int blk = blockIdx.x;
    int b = blk >> 6, h = (blk >> 3) & 7, it = blk & 7;

    for (int f = tid; f < 8192; f += 256) {
        int j = f >> 6, k = f & 63;
        Vs[f] = g_Vh[(long)(b * 128 + j) * 512 + h * 64 + k];
    }
    if (tid < 128) ms[tid] = mask[b * 128 + tid];
    __syncthreads();

#pragma unroll
    for (int rr = 0; rr < 2; ++rr) {
        int i = it * 16 + warp * 2 + rr;
        float mi = ms[i];
        float pm[4];
        float den = 0.0f;
#pragma unroll
        for (int m = 0; m < 4; ++m) {
            int j = m * 32 + lane;
            float s = g_sc[((long)((b * 8 + h) * 128 + i)) * 128 + j];
            float p = __expf(s) * ms[j] * krw[(long)b * 16384 + i * 128 + j];
            pm[m] = p;
            den += p;
        }
#pragma unroll
        for (int o = 16; o; o >>= 1) den += __shfl_xor_sync(0xffffffffu, den, o);
        den = fmaxf(den * mi, 1e-6f);

        float a0 = 0.0f, a1 = 0.0f;
#pragma unroll
        for (int m = 0; m < 4; ++m) {
#pragma unroll 8
            for (int jj = 0; jj < 32; ++jj) {
                float p = __shfl_sync(0xffffffffu, pm[m], jj);
                int j = m * 32 + jj;
                a0 += p * Vs[j * 64 + lane];
                a1 += p * Vs[j * 64 + lane + 32];
            }
        }
        float inv = mi / den;
        long ob = (long)(b * 128 + i) * 512 + h * 64;
        out[ob + lane] = a0 * inv;
        out[ob + lane + 32] = a1 * inv;
    }
}

// ---------------------------------------------------------------------------
extern "C" void kernel_launch(void* const* d_in, const int* in_sizes, int n_in,
                              void* d_out, int out_size)
{
    (void)in_sizes; (void)n_in; (void)out_size;
    const float*    h    = (const float*)d_in[0];
    const float*    e    = (const float*)d_in[1];
    const float*    krw  = (const float*)d_in[2];
    const float*    mask = (const float*)d_in[3];
    const unsigned* adjw = (const unsigned*)d_in[4];
    const float*    Wq   = (const float*)d_in[5];
    const float*    Wk   = (const float*)d_in[6];
    const float*    Wv   = (const float*)d_in[7];
    const float*    We   = (const float*)d_in[8];
    const float*    Wq2  = (const float*)d_in[9];
    const float*    Wk2  = (const float*)d_in[10];
    const float*    We2  = (const float*)d_in[11];
    float* out = (float*)d_out;

    cudaFuncSetAttribute(proj_kernel,
                         cudaFuncAttributeMaxDynamicSharedMemorySize, 65536);
    // score smem: (9216 + 512 + 512 + 1024)*4 + 8 + 544 = 45608 -> 45632
    cudaFuncSetAttribute(score_kernel,
                         cudaFuncAttributeMaxDynamicSharedMemorySize, 45632);

    transpose_kernel<<<dim3(16, 4, 7), 256>>>(Wq, Wk, Wv, Wq2, Wk2, We, We2);
    proj_kernel<<<dim3(8, 16, 5), 256, 65536>>>(h);
    score_kernel<<<1024, 512, 45632>>>(e, adjw);
    out_kernel<<<512, 256>>>(krw, mask, out);
}